// round 1
// baseline (speedup 1.0000x reference)
#include <cuda_runtime.h>

#define BS    32
#define EMB   512
#define GL    256
#define NOUT  64
#define NIN   64
#define WFLAT 36864   // NOUT*NIN*9
#define HIN   96
#define HOUT  94

// Scratch (allocation-free): hypernetwork intermediates
__device__ __align__(16) float g_hdn[BS * GL];          // [s][j]  32 KB
__device__ __align__(16) float g_wt [BS * WFLAT];       // [s][oc*576+ic*9+kk]  4.7 MB

// ---------------------------------------------------------------------------
// Kernel 1: hdn[s][j] = relu(sum_k emb[s,k]*w1[j,k] + b1[j])
// grid=32 (sample), block=256 (j)
// ---------------------------------------------------------------------------
__global__ void hyper1(const float* __restrict__ emb,
                       const float* __restrict__ w1w,
                       const float* __restrict__ w1b) {
    __shared__ float semb[EMB];
    const int s = blockIdx.x;
    const int j = threadIdx.x;
    semb[j]       = emb[s * EMB + j];
    semb[j + 256] = emb[s * EMB + j + 256];
    __syncthreads();

    const float4* wr = (const float4*)(w1w + (size_t)j * EMB);
    const float4* er = (const float4*)semb;
    float acc = 0.f;
#pragma unroll 8
    for (int k = 0; k < EMB / 4; k++) {
        float4 w = wr[k];
        float4 e = er[k];
        acc += w.x * e.x + w.y * e.y + w.z * e.z + w.w * e.w;
    }
    acc += w1b[j];
    g_hdn[s * GL + j] = acc > 0.f ? acc : 0.f;
}

// ---------------------------------------------------------------------------
// Kernel 2: g_wt[s][row] = sum_k hdn[s,k]*w2[row,k] + b2[row]
// GEMM [36864 x 256] x [256 x 32].
// Block: 128 threads = 32 row-lanes x 4 sample-groups; thread owns 8 samples.
//  - w2 tile transposed into smem [k][row+pad] -> conflict-free vector LDS.
//  - hdn in smem [s][k] -> k-vectorized float4 broadcast LDS (warp-uniform s).
// grid = 36864/32 = 1152.
// ---------------------------------------------------------------------------
__global__ __launch_bounds__(128) void hyper2(const float* __restrict__ w2w,
                                              const float* __restrict__ w2b) {
    __shared__ float hdn_sm[BS * GL];   // 32 KB, [s][k]
    __shared__ float w2t[64 * 33];      // 8.4 KB, [kk][row] padded stride 33

    const int tid  = threadIdx.x;
    const int lane = tid & 31;   // row within block
    const int sg   = tid >> 5;   // sample group 0..3 (8 samples each)
    const int r0   = blockIdx.x * 32;

    // stage hdn (2048 float4 over 128 threads)
#pragma unroll
    for (int it = 0; it < 16; it++)
        ((float4*)hdn_sm)[it * 128 + tid] = ((const float4*)g_hdn)[it * 128 + tid];

    float acc[8];
#pragma unroll
    for (int i = 0; i < 8; i++) acc[i] = 0.f;

    for (int kc = 0; kc < 4; kc++) {
        __syncthreads();   // hdn staged / previous chunk consumed
        // stage w2 tile transposed: 32 rows x 64 k
#pragma unroll
        for (int it = 0; it < 16; it++) {
            int idx = it * 128 + tid;
            int r = idx >> 6, kk = idx & 63;
            w2t[kk * 33 + r] = w2w[(size_t)(r0 + r) * GL + kc * 64 + kk];
        }
        __syncthreads();

#pragma unroll
        for (int k = 0; k < 64; k += 4) {
            const float wa = w2t[(k + 0) * 33 + lane];
            const float wb = w2t[(k + 1) * 33 + lane];
            const float wc = w2t[(k + 2) * 33 + lane];
            const float wd = w2t[(k + 3) * 33 + lane];
#pragma unroll
            for (int si = 0; si < 8; si++) {
                const float4 h = *(const float4*)&hdn_sm[(sg * 8 + si) * GL + kc * 64 + k];
                acc[si] += wa * h.x + wb * h.y + wc * h.z + wd * h.w;
            }
        }
    }

    const int row = r0 + lane;
    const float b = w2b[row];
#pragma unroll
    for (int si = 0; si < 8; si++)
        g_wt[(size_t)(sg * 8 + si) * WFLAT + row] = acc[si] + b;   // coalesced across lanes
}

// ---------------------------------------------------------------------------
// Kernel 3: per-sample 3x3 valid conv, 64->64 channels.
// Block = 256 thr (16x16 groups), each thread: 16 oc x 2x2 spatial = 64 accs.
// Spatial tile 32x32 output; ic chunked by 4 through smem.
// Weight LDS are block-uniform (broadcast); FMA pipe is the bottleneck.
// grid = (9 tiles, 4 oc-groups, 32 samples)
// ---------------------------------------------------------------------------
__global__ __launch_bounds__(256) void convk(const float* __restrict__ x,
                                             float* __restrict__ out) {
    __shared__ float sIn[4][34 * 34];   // 18.5 KB
    __shared__ float sW[16 * 4 * 9];    // 2.3 KB  [o][icl][kk]

    const int s   = blockIdx.z;
    const int ocg = blockIdx.y;
    const int th  = blockIdx.x / 3;
    const int tw  = blockIdx.x % 3;
    const int h0  = th * 32, w0 = tw * 32;
    const int tid = threadIdx.x;
    const int tx  = tid & 15, ty = tid >> 4;

    const float* xs = x + (size_t)s * NIN * HIN * HIN;
    const float* ws = g_wt + (size_t)s * WFLAT + (size_t)(ocg * 16) * 576;

    float A[64];
#pragma unroll
    for (int i = 0; i < 64; i++) A[i] = 0.f;

#pragma unroll 1
    for (int ic0 = 0; ic0 < NIN; ic0 += 4) {
        __syncthreads();   // previous chunk fully consumed
        // stage input: 4 ch x 34x34 (zero-fill out of range)
#pragma unroll
        for (int it = 0; it < 19; it++) {
            int idx = it * 256 + tid;
            if (idx < 4 * 1156) {
                int icl = idx / 1156;
                int rem = idx - icl * 1156;
                int i = rem / 34, j = rem - i * 34;
                int gh = h0 + i, gw = w0 + j;
                float v = 0.f;
                if (gh < HIN && gw < HIN)
                    v = xs[(size_t)(ic0 + icl) * (HIN * HIN) + gh * HIN + gw];
                sIn[icl][rem] = v;
            }
        }
        // stage weights: 16 oc x 4 ic x 9
        {
            int idx = tid;
#pragma unroll
            for (int it = 0; it < 3; it++, idx += 256) {
                if (idx < 576) {
                    int o = idx / 36;
                    int rem = idx - o * 36;
                    int icl = rem / 9;
                    int kk  = rem - icl * 9;
                    sW[idx] = ws[o * 576 + (ic0 + icl) * 9 + kk];
                }
            }
        }
        __syncthreads();

#pragma unroll 1
        for (int icl = 0; icl < 4; icl++) {
            float p[4][4];
#pragma unroll
            for (int di = 0; di < 4; di++)
#pragma unroll
                for (int dj = 0; dj < 4; dj++)
                    p[di][dj] = sIn[icl][(2 * ty + di) * 34 + 2 * tx + dj];

#pragma unroll
            for (int o = 0; o < 16; o++) {
#pragma unroll
                for (int kh = 0; kh < 3; kh++)
#pragma unroll
                    for (int kw = 0; kw < 3; kw++) {
                        const float w = sW[o * 36 + icl * 9 + kh * 3 + kw];
                        A[o * 4 + 0] += w * p[kh][kw];
                        A[o * 4 + 1] += w * p[kh][kw + 1];
                        A[o * 4 + 2] += w * p[kh + 1][kw];
                        A[o * 4 + 3] += w * p[kh + 1][kw + 1];
                    }
            }
        }
    }

    // epilogue: guarded stores (94x94 valid region)
    const int hb = h0 + 2 * ty;
    const int wb = w0 + 2 * tx;
#pragma unroll
    for (int o = 0; o < 16; o++) {
        const size_t cbase = (size_t)(s * NOUT + ocg * 16 + o) * HOUT;
#pragma unroll
        for (int dh = 0; dh < 2; dh++) {
            const int h = hb + dh;
            if (h < HOUT) {
#pragma unroll
                for (int dw = 0; dw < 2; dw++) {
                    const int w = wb + dw;
                    if (w < HOUT)
                        out[(cbase + h) * HOUT + w] = A[o * 4 + dh * 2 + dw];
                }
            }
        }
    }
}

// ---------------------------------------------------------------------------
extern "C" void kernel_launch(void* const* d_in, const int* in_sizes, int n_in,
                              void* d_out, int out_size) {
    const float* emb = (const float*)d_in[0];   // [32,512]
    const float* x   = (const float*)d_in[1];   // [32,64,96,96]
    const float* w1w = (const float*)d_in[2];   // [256,512]
    const float* w1b = (const float*)d_in[3];   // [256]
    const float* w2w = (const float*)d_in[4];   // [36864,256]
    const float* w2b = (const float*)d_in[5];   // [36864]
    float* out = (float*)d_out;                 // [32,64,94,94]

    hyper1<<<32, 256>>>(emb, w1w, w1b);
    hyper2<<<WFLAT / 32, 128>>>(w2w, w2b);
    convk<<<dim3(9, 4, 32), 256>>>(x, out);
}

// round 2
// speedup vs baseline: 1.1775x; 1.1775x over previous
#include <cuda_runtime.h>

#define BS    32
#define EMB   512
#define GL    256
#define NOUT  64
#define NIN   64
#define WFLAT 36864   // NOUT*NIN*9
#define HIN   96
#define HOUT  94

typedef unsigned long long u64;

// Scratch (allocation-free)
__device__ __align__(16) float g_hdn_t[GL * BS];        // [j][s] transposed, 32 KB
__device__ __align__(16) float g_wt  [BS * WFLAT];      // [s][oc*576+ic*9+kk] 4.7 MB

// ---- packed f32x2 helpers -------------------------------------------------
__device__ __forceinline__ void fma2(u64& d, u64 a, u64 b) {
    asm("fma.rn.f32x2 %0, %1, %2, %0;" : "+l"(d) : "l"(a), "l"(b));
}
__device__ __forceinline__ u64 dup2(float v) {
    u64 r; asm("mov.b64 %0, {%1, %1};" : "=l"(r) : "f"(v)); return r;
}
__device__ __forceinline__ void unpk2(u64 v, float& lo, float& hi) {
    asm("mov.b64 {%0, %1}, %2;" : "=f"(lo), "=f"(hi) : "l"(v));
}

// ---------------------------------------------------------------------------
// Kernel 1: hdn_t[j][s] = relu(emb[s,:]·w1[j,:] + b1[j])
// grid = 256 (32 samples x 8 j-groups), block 256 = 32 j-lanes x 8 k-slices
// ---------------------------------------------------------------------------
__global__ __launch_bounds__(256) void hyper1(const float* __restrict__ emb,
                                              const float* __restrict__ w1w,
                                              const float* __restrict__ w1b) {
    __shared__ float red[8][33];
    const int tid   = threadIdx.x;
    const int s     = blockIdx.x >> 3;
    const int jg    = blockIdx.x & 7;
    const int lane  = tid & 31;
    const int slice = tid >> 5;
    const int j     = jg * 32 + lane;

    const float4* wr = (const float4*)(w1w + (size_t)j * EMB + slice * 64);
    const float4* er = (const float4*)(emb + (size_t)s * EMB + slice * 64);
    float acc = 0.f;
#pragma unroll
    for (int k = 0; k < 16; k++) {
        float4 w = wr[k], e = er[k];
        acc += w.x * e.x + w.y * e.y + w.z * e.z + w.w * e.w;
    }
    red[slice][lane] = acc;
    __syncthreads();
    if (tid < 32) {
        float a = 0.f;
#pragma unroll
        for (int t = 0; t < 8; t++) a += red[t][tid];
        const int jj = jg * 32 + tid;
        a += w1b[jj];
        g_hdn_t[jj * BS + s] = a > 0.f ? a : 0.f;
    }
}

// ---------------------------------------------------------------------------
// Kernel 2: g_wt[s][row] = hdn[s,:]·w2[row,:] + b2[row]   (f32x2 over samples)
// Block 128 = 32 row-lanes x 4 warps; warp owns 8 samples = 4 packed pairs.
// ---------------------------------------------------------------------------
__global__ __launch_bounds__(128) void hyper2(const float* __restrict__ w2w,
                                              const float* __restrict__ w2b) {
    __shared__ float  hdn_sm[GL * BS];       // [k][s], 32 KB
    __shared__ __align__(16) float2 w2td[64 * 33];   // duplicated (w,w), 16.9 KB

    const int tid  = threadIdx.x;
    const int lane = tid & 31;   // row within block
    const int sg   = tid >> 5;   // sample group 0..3
    const int r0   = blockIdx.x * 32;

#pragma unroll
    for (int it = 0; it < 16; it++)
        ((float4*)hdn_sm)[it * 128 + tid] = ((const float4*)g_hdn_t)[it * 128 + tid];

    u64 acc2[4];
#pragma unroll
    for (int i = 0; i < 4; i++) acc2[i] = 0ull;

    for (int kc = 0; kc < 4; kc++) {
        __syncthreads();
#pragma unroll
        for (int it = 0; it < 16; it++) {
            int idx = it * 128 + tid;
            int r = idx >> 6, kk = idx & 63;
            float v = w2w[(size_t)(r0 + r) * GL + kc * 64 + kk];
            w2td[kk * 33 + r] = make_float2(v, v);
        }
        __syncthreads();

#pragma unroll
        for (int k = 0; k < 64; k++) {
            const u64 wd = *(const u64*)&w2td[k * 33 + lane];
            const float* hb = &hdn_sm[(kc * 64 + k) * BS + sg * 8];
            fma2(acc2[0], wd, *(const u64*)&hb[0]);
            fma2(acc2[1], wd, *(const u64*)&hb[2]);
            fma2(acc2[2], wd, *(const u64*)&hb[4]);
            fma2(acc2[3], wd, *(const u64*)&hb[6]);
        }
    }

    const int row = r0 + lane;
    const float b = w2b[row];
#pragma unroll
    for (int pi = 0; pi < 4; pi++) {
        float lo, hi;
        unpk2(acc2[pi], lo, hi);
        g_wt[(size_t)(sg * 8 + 2 * pi + 0) * WFLAT + row] = lo + b;
        g_wt[(size_t)(sg * 8 + 2 * pi + 1) * WFLAT + row] = hi + b;
    }
}

// ---------------------------------------------------------------------------
// Kernel 3: per-sample 3x3 valid conv, 64->64 ch, packed f32x2 over oc pairs.
// Block 256 (16x16), thread: 8 oc-pairs x 2x2 spatial = 32 packed accs.
// grid = (9 tiles, 4 oc-groups, 32 samples)
// ---------------------------------------------------------------------------
__global__ __launch_bounds__(256) void convk(const float* __restrict__ x,
                                             float* __restrict__ out) {
    __shared__ float sIn[4][34 * 34];                    // 18.5 KB
    __shared__ __align__(16) float sW[4 * 9 * 16];       // [icl][kk][oc], 2.3 KB

    const int s   = blockIdx.z;
    const int ocg = blockIdx.y;
    const int th  = blockIdx.x / 3;
    const int tw  = blockIdx.x % 3;
    const int h0  = th * 32, w0 = tw * 32;
    const int tid = threadIdx.x;
    const int tx  = tid & 15, ty = tid >> 4;

    const float* xs = x + (size_t)s * NIN * HIN * HIN;
    const float* ws = g_wt + (size_t)s * WFLAT + (size_t)(ocg * 16) * 576;

    u64 A2[32];
#pragma unroll
    for (int i = 0; i < 32; i++) A2[i] = 0ull;

#pragma unroll 1
    for (int ic0 = 0; ic0 < NIN; ic0 += 4) {
        __syncthreads();
        // stage input: 4 ch x 34x34 (zero-fill out of range)
#pragma unroll
        for (int it = 0; it < 19; it++) {
            int idx = it * 256 + tid;
            if (idx < 4 * 1156) {
                int icl = idx / 1156;
                int rem = idx - icl * 1156;
                int i = rem / 34, jc = rem - i * 34;
                int gh = h0 + i, gw = w0 + jc;
                float v = 0.f;
                if (gh < HIN && gw < HIN)
                    v = xs[(size_t)(ic0 + icl) * (HIN * HIN) + gh * HIN + gw];
                sIn[icl][rem] = v;
            }
        }
        // stage weights: [icl][kk][oc], oc contiguous for packed LDS.64
        {
            int idx = tid;
#pragma unroll
            for (int it = 0; it < 3; it++, idx += 256) {
                if (idx < 576) {
                    int o   = idx & 15;
                    int kk  = (idx >> 4) % 9;
                    int icl = (idx >> 4) / 9;
                    sW[idx] = ws[o * 576 + (ic0 + icl) * 9 + kk];
                }
            }
        }
        __syncthreads();

#pragma unroll 1
        for (int icl = 0; icl < 4; icl++) {
            float p[4][4];
#pragma unroll
            for (int di = 0; di < 4; di++)
#pragma unroll
                for (int dj = 0; dj < 4; dj++)
                    p[di][dj] = sIn[icl][(2 * ty + di) * 34 + 2 * tx + dj];

#pragma unroll
            for (int kh = 0; kh < 3; kh++)
#pragma unroll
                for (int kw = 0; kw < 3; kw++) {
                    const u64 pa = dup2(p[kh    ][kw    ]);
                    const u64 pb = dup2(p[kh    ][kw + 1]);
                    const u64 pc = dup2(p[kh + 1][kw    ]);
                    const u64 pd = dup2(p[kh + 1][kw + 1]);
                    const float* wrow = &sW[(icl * 9 + kh * 3 + kw) * 16];
#pragma unroll
                    for (int o2 = 0; o2 < 8; o2++) {
                        const u64 wv = *(const u64*)&wrow[o2 * 2];
                        fma2(A2[o2 * 4 + 0], wv, pa);
                        fma2(A2[o2 * 4 + 1], wv, pb);
                        fma2(A2[o2 * 4 + 2], wv, pc);
                        fma2(A2[o2 * 4 + 3], wv, pd);
                    }
                }
        }
    }

    // epilogue: unpack oc pairs, guarded stores (94x94 valid)
    const int hb = h0 + 2 * ty;
    const int wb = w0 + 2 * tx;
#pragma unroll
    for (int o2 = 0; o2 < 8; o2++) {
        const size_t c0 = (size_t)(s * NOUT + ocg * 16 + o2 * 2 + 0) * HOUT;
        const size_t c1 = (size_t)(s * NOUT + ocg * 16 + o2 * 2 + 1) * HOUT;
#pragma unroll
        for (int dh = 0; dh < 2; dh++) {
            const int h = hb + dh;
            if (h >= HOUT) continue;
#pragma unroll
            for (int dw = 0; dw < 2; dw++) {
                const int w = wb + dw;
                if (w >= HOUT) continue;
                float lo, hi;
                unpk2(A2[o2 * 4 + dh * 2 + dw], lo, hi);
                out[(c0 + h) * HOUT + w] = lo;
                out[(c1 + h) * HOUT + w] = hi;
            }
        }
    }
}

// ---------------------------------------------------------------------------
extern "C" void kernel_launch(void* const* d_in, const int* in_sizes, int n_in,
                              void* d_out, int out_size) {
    const float* emb = (const float*)d_in[0];
    const float* x   = (const float*)d_in[1];
    const float* w1w = (const float*)d_in[2];
    const float* w1b = (const float*)d_in[3];
    const float* w2w = (const float*)d_in[4];
    const float* w2b = (const float*)d_in[5];
    float* out = (float*)d_out;

    hyper1<<<256, 256>>>(emb, w1w, w1b);
    hyper2<<<WFLAT / 32, 128>>>(w2w, w2b);
    convk<<<dim3(9, 4, 32), 256>>>(x, out);
}

// round 3
// speedup vs baseline: 1.1791x; 1.0014x over previous
#include <cuda_runtime.h>

#define BS    32
#define EMB   512
#define GL    256
#define NOUT  64
#define NIN   64
#define WFLAT 36864   // NOUT*NIN*9
#define HIN   96
#define HOUT  94

typedef unsigned long long u64;

// Scratch (allocation-free)
__device__ __align__(16) float g_hdn_t[GL * BS];        // [j][s] transposed, 32 KB
__device__ __align__(16) float g_wt  [BS * WFLAT];      // [s][oc*576+ic*9+kk] 4.7 MB

// ---- packed f32x2 helpers -------------------------------------------------
__device__ __forceinline__ void fma2(u64& d, u64 a, u64 b) {
    asm("fma.rn.f32x2 %0, %1, %2, %0;" : "+l"(d) : "l"(a), "l"(b));
}
__device__ __forceinline__ u64 dup2(float v) {
    u64 r; asm("mov.b64 %0, {%1, %1};" : "=l"(r) : "f"(v)); return r;
}
__device__ __forceinline__ void unpk2(u64 v, float& lo, float& hi) {
    asm("mov.b64 {%0, %1}, %2;" : "=f"(lo), "=f"(hi) : "l"(v));
}

// ---------------------------------------------------------------------------
// Kernel 1: hdn_t[j][s] = relu(emb[s,:]·w1[j,:] + b1[j])
// grid = 256 (32 samples x 8 j-groups), block 256 = 32 j-lanes x 8 k-slices
// ---------------------------------------------------------------------------
__global__ __launch_bounds__(256) void hyper1(const float* __restrict__ emb,
                                              const float* __restrict__ w1w,
                                              const float* __restrict__ w1b) {
    __shared__ float red[8][33];
    const int tid   = threadIdx.x;
    const int s     = blockIdx.x >> 3;
    const int jg    = blockIdx.x & 7;
    const int lane  = tid & 31;
    const int slice = tid >> 5;
    const int j     = jg * 32 + lane;

    const float4* wr = (const float4*)(w1w + (size_t)j * EMB + slice * 64);
    const float4* er = (const float4*)(emb + (size_t)s * EMB + slice * 64);
    float acc = 0.f;
#pragma unroll
    for (int k = 0; k < 16; k++) {
        float4 w = wr[k], e = er[k];
        acc += w.x * e.x + w.y * e.y + w.z * e.z + w.w * e.w;
    }
    red[slice][lane] = acc;
    __syncthreads();
    if (tid < 32) {
        float a = 0.f;
#pragma unroll
        for (int t = 0; t < 8; t++) a += red[t][tid];
        const int jj = jg * 32 + tid;
        a += w1b[jj];
        g_hdn_t[jj * BS + s] = a > 0.f ? a : 0.f;
    }
}

// ---------------------------------------------------------------------------
// Kernel 2: g_wt[s][row] = hdn[s,:]·w2[row,:] + b2[row]   (f32x2 over samples)
// Block 128 = 32 row-lanes x 4 warps; warp owns 8 samples = 4 packed pairs.
// ---------------------------------------------------------------------------
__global__ __launch_bounds__(128) void hyper2(const float* __restrict__ w2w,
                                              const float* __restrict__ w2b) {
    __shared__ float  hdn_sm[GL * BS];       // [k][s], 32 KB
    __shared__ __align__(16) float2 w2td[64 * 33];   // duplicated (w,w), 16.9 KB

    const int tid  = threadIdx.x;
    const int lane = tid & 31;   // row within block
    const int sg   = tid >> 5;   // sample group 0..3
    const int r0   = blockIdx.x * 32;

#pragma unroll
    for (int it = 0; it < 16; it++)
        ((float4*)hdn_sm)[it * 128 + tid] = ((const float4*)g_hdn_t)[it * 128 + tid];

    u64 acc2[4];
#pragma unroll
    for (int i = 0; i < 4; i++) acc2[i] = 0ull;

    for (int kc = 0; kc < 4; kc++) {
        __syncthreads();
#pragma unroll
        for (int it = 0; it < 16; it++) {
            int idx = it * 128 + tid;
            int r = idx >> 6, kk = idx & 63;
            float v = w2w[(size_t)(r0 + r) * GL + kc * 64 + kk];
            w2td[kk * 33 + r] = make_float2(v, v);
        }
        __syncthreads();

#pragma unroll
        for (int k = 0; k < 64; k++) {
            const u64 wd = *(const u64*)&w2td[k * 33 + lane];
            const float* hb = &hdn_sm[(kc * 64 + k) * BS + sg * 8];
            fma2(acc2[0], wd, *(const u64*)&hb[0]);
            fma2(acc2[1], wd, *(const u64*)&hb[2]);
            fma2(acc2[2], wd, *(const u64*)&hb[4]);
            fma2(acc2[3], wd, *(const u64*)&hb[6]);
        }
    }

    const int row = r0 + lane;
    const float b = w2b[row];
#pragma unroll
    for (int pi = 0; pi < 4; pi++) {
        float lo, hi;
        unpk2(acc2[pi], lo, hi);
        g_wt[(size_t)(sg * 8 + 2 * pi + 0) * WFLAT + row] = lo + b;
        g_wt[(size_t)(sg * 8 + 2 * pi + 1) * WFLAT + row] = hi + b;
    }
}

// ---------------------------------------------------------------------------
// Kernel 3: per-sample 3x3 valid conv, 64->64 ch, packed f32x2 over oc pairs.
// Block 256 (16x16), thread: 8 oc-pairs x 2x2 spatial = 32 packed accs.
// grid = (9 tiles, 4 oc-groups, 32 samples)
// ---------------------------------------------------------------------------
__global__ __launch_bounds__(256) void convk(const float* __restrict__ x,
                                             float* __restrict__ out) {
    __shared__ float sIn[4][34 * 34];                    // 18.5 KB
    __shared__ __align__(16) float sW[4 * 9 * 16];       // [icl][kk][oc], 2.3 KB

    const int s   = blockIdx.z;
    const int ocg = blockIdx.y;
    const int th  = blockIdx.x / 3;
    const int tw  = blockIdx.x % 3;
    const int h0  = th * 32, w0 = tw * 32;
    const int tid = threadIdx.x;
    const int tx  = tid & 15, ty = tid >> 4;

    const float* xs = x + (size_t)s * NIN * HIN * HIN;
    const float* ws = g_wt + (size_t)s * WFLAT + (size_t)(ocg * 16) * 576;

    u64 A2[32];
#pragma unroll
    for (int i = 0; i < 32; i++) A2[i] = 0ull;

#pragma unroll 1
    for (int ic0 = 0; ic0 < NIN; ic0 += 4) {
        __syncthreads();
        // stage input: 4 ch x 34x34 (zero-fill out of range)
#pragma unroll
        for (int it = 0; it < 19; it++) {
            int idx = it * 256 + tid;
            if (idx < 4 * 1156) {
                int icl = idx / 1156;
                int rem = idx - icl * 1156;
                int i = rem / 34, jc = rem - i * 34;
                int gh = h0 + i, gw = w0 + jc;
                float v = 0.f;
                if (gh < HIN && gw < HIN)
                    v = xs[(size_t)(ic0 + icl) * (HIN * HIN) + gh * HIN + gw];
                sIn[icl][rem] = v;
            }
        }
        // stage weights: [icl][kk][oc], oc contiguous for packed LDS.64
        {
            int idx = tid;
#pragma unroll
            for (int it = 0; it < 3; it++, idx += 256) {
                if (idx < 576) {
                    int o   = idx & 15;
                    int kk  = (idx >> 4) % 9;
                    int icl = (idx >> 4) / 9;
                    sW[idx] = ws[o * 576 + (ic0 + icl) * 9 + kk];
                }
            }
        }
        __syncthreads();

#pragma unroll 1
        for (int icl = 0; icl < 4; icl++) {
            float p[4][4];
#pragma unroll
            for (int di = 0; di < 4; di++)
#pragma unroll
                for (int dj = 0; dj < 4; dj++)
                    p[di][dj] = sIn[icl][(2 * ty + di) * 34 + 2 * tx + dj];

#pragma unroll
            for (int kh = 0; kh < 3; kh++)
#pragma unroll
                for (int kw = 0; kw < 3; kw++) {
                    const u64 pa = dup2(p[kh    ][kw    ]);
                    const u64 pb = dup2(p[kh    ][kw + 1]);
                    const u64 pc = dup2(p[kh + 1][kw    ]);
                    const u64 pd = dup2(p[kh + 1][kw + 1]);
                    const float* wrow = &sW[(icl * 9 + kh * 3 + kw) * 16];
#pragma unroll
                    for (int o2 = 0; o2 < 8; o2++) {
                        const u64 wv = *(const u64*)&wrow[o2 * 2];
                        fma2(A2[o2 * 4 + 0], wv, pa);
                        fma2(A2[o2 * 4 + 1], wv, pb);
                        fma2(A2[o2 * 4 + 2], wv, pc);
                        fma2(A2[o2 * 4 + 3], wv, pd);
                    }
                }
        }
    }

    // epilogue: unpack oc pairs, guarded stores (94x94 valid)
    const int hb = h0 + 2 * ty;
    const int wb = w0 + 2 * tx;
#pragma unroll
    for (int o2 = 0; o2 < 8; o2++) {
        const size_t c0 = (size_t)(s * NOUT + ocg * 16 + o2 * 2 + 0) * HOUT;
        const size_t c1 = (size_t)(s * NOUT + ocg * 16 + o2 * 2 + 1) * HOUT;
#pragma unroll
        for (int dh = 0; dh < 2; dh++) {
            const int h = hb + dh;
            if (h >= HOUT) continue;
#pragma unroll
            for (int dw = 0; dw < 2; dw++) {
                const int w = wb + dw;
                if (w >= HOUT) continue;
                float lo, hi;
                unpk2(A2[o2 * 4 + dh * 2 + dw], lo, hi);
                out[(c0 + h) * HOUT + w] = lo;
                out[(c1 + h) * HOUT + w] = hi;
            }
        }
    }
}

// ---------------------------------------------------------------------------
extern "C" void kernel_launch(void* const* d_in, const int* in_sizes, int n_in,
                              void* d_out, int out_size) {
    const float* emb = (const float*)d_in[0];
    const float* x   = (const float*)d_in[1];
    const float* w1w = (const float*)d_in[2];
    const float* w1b = (const float*)d_in[3];
    const float* w2w = (const float*)d_in[4];
    const float* w2b = (const float*)d_in[5];
    float* out = (float*)d_out;

    hyper1<<<256, 256>>>(emb, w1w, w1b);
    hyper2<<<WFLAT / 32, 128>>>(w2w, w2b);
    convk<<<dim3(9, 4, 32), 256>>>(x, out);
}

// round 5
// speedup vs baseline: 1.7243x; 1.4624x over previous
#include <cuda_runtime.h>
#include <cstdint>

#define BS    32
#define EMB   512
#define GL    256
#define WFLAT 36864
#define HIN   96
#define HOUT  94
#define NPIX  9216
#define XMAXI (32u*64u*9216u - 1u)

typedef unsigned long long u64;
typedef unsigned int u32;

__device__ __align__(16) float g_hdn_t[GL * BS];
// B in mma-fragment order: [s][kk][ks(8)][nt(8)][lane(32)][2], tf32-rounded
__device__ __align__(16) float g_wt2 [BS * WFLAT];

// ---- helpers ----------------------------------------------------------------
__device__ __forceinline__ void fma2(u64& d, u64 a, u64 b) {
    asm("fma.rn.f32x2 %0, %1, %2, %0;" : "+l"(d) : "l"(a), "l"(b));
}
__device__ __forceinline__ void unpk2(u64 v, float& lo, float& hi) {
    asm("mov.b64 {%0, %1}, %2;" : "=f"(lo), "=f"(hi) : "l"(v));
}
__device__ __forceinline__ float rna_tf32(float v) {
    u32 u; asm("cvt.rna.tf32.f32 %0, %1;" : "=r"(u) : "f"(v));
    return __uint_as_float(u);
}
// tf32 warp MMA: D(16x8) += A(16x8) * B(8x8);  A row-major, B col-major frags
__device__ __forceinline__ void mma8(float* c, u32 a0, u32 a1, u32 a2, u32 a3,
                                     u32 b0, u32 b1) {
    asm("mma.sync.aligned.m16n8k8.row.col.f32.tf32.tf32.f32 "
        "{%0,%1,%2,%3}, {%4,%5,%6,%7}, {%8,%9}, {%0,%1,%2,%3};"
        : "+f"(c[0]), "+f"(c[1]), "+f"(c[2]), "+f"(c[3])
        : "r"(a0), "r"(a1), "r"(a2), "r"(a3), "r"(b0), "r"(b1));
}

// ---------------------------------------------------------------------------
// hyper1: hdn_t[j][s] = relu(emb[s,:]·w1[j,:] + b1[j])
// ---------------------------------------------------------------------------
__global__ __launch_bounds__(256) void hyper1(const float* __restrict__ emb,
                                              const float* __restrict__ w1w,
                                              const float* __restrict__ w1b) {
    __shared__ float red[8][33];
    const int tid = threadIdx.x;
    const int s = blockIdx.x >> 3, jg = blockIdx.x & 7;
    const int lane = tid & 31, slice = tid >> 5;
    const int j = jg * 32 + lane;
    const float4* wr = (const float4*)(w1w + (size_t)j * EMB + slice * 64);
    const float4* er = (const float4*)(emb + (size_t)s * EMB + slice * 64);
    float acc = 0.f;
#pragma unroll
    for (int k = 0; k < 16; k++) {
        float4 w = wr[k], e = er[k];
        acc += w.x * e.x + w.y * e.y + w.z * e.z + w.w * e.w;
    }
    red[slice][lane] = acc;
    __syncthreads();
    if (tid < 32) {
        float a = 0.f;
#pragma unroll
        for (int t = 0; t < 8; t++) a += red[t][tid];
        const int jj = jg * 32 + tid;
        a += w1b[jj];
        g_hdn_t[jj * BS + s] = a > 0.f ? a : 0.f;
    }
}

// ---------------------------------------------------------------------------
// hyper2: weight GEMM; epilogue writes tf32-rounded values in mma B-fragment
// order: off = ((((s*9+kk)*8+ks)*8+nt)*32 + lane)*2 + reg
//   where row = oc*576+ic*9+kk, ks=ic>>3, nt=oc>>3,
//         lane = (oc&7)*4 + (ic&3), reg = (ic>>2)&1
// ---------------------------------------------------------------------------
__global__ __launch_bounds__(128) void hyper2(const float* __restrict__ w2w,
                                              const float* __restrict__ w2b) {
    __shared__ float hdn_sm[GL * BS];
    __shared__ __align__(16) float2 w2td[64 * 33];

    const int tid = threadIdx.x;
    const int lane = tid & 31, sg = tid >> 5;
    const int r0 = blockIdx.x * 32;

#pragma unroll
    for (int it = 0; it < 16; it++)
        ((float4*)hdn_sm)[it * 128 + tid] = ((const float4*)g_hdn_t)[it * 128 + tid];

    u64 acc2[4];
#pragma unroll
    for (int i = 0; i < 4; i++) acc2[i] = 0ull;

    for (int kc = 0; kc < 4; kc++) {
        __syncthreads();
#pragma unroll
        for (int it = 0; it < 16; it++) {
            int idx = it * 128 + tid;
            int r = idx >> 6, kk = idx & 63;
            float v = w2w[(size_t)(r0 + r) * GL + kc * 64 + kk];
            w2td[kk * 33 + r] = make_float2(v, v);
        }
        __syncthreads();
#pragma unroll
        for (int k = 0; k < 64; k++) {
            const u64 wd = *(const u64*)&w2td[k * 33 + lane];
            const float* hb = &hdn_sm[(kc * 64 + k) * BS + sg * 8];
            fma2(acc2[0], wd, *(const u64*)&hb[0]);
            fma2(acc2[1], wd, *(const u64*)&hb[2]);
            fma2(acc2[2], wd, *(const u64*)&hb[4]);
            fma2(acc2[3], wd, *(const u64*)&hb[6]);
        }
    }

    const int row = r0 + lane;          // row = oc*576 + ic*9 + kk
    const int oc  = row / 576;
    const int rem = row - oc * 576;
    const int ic  = rem / 9;
    const int kk  = rem - ic * 9;
    const int frag = (((kk * 8 + (ic >> 3)) * 8 + (oc >> 3)) * 32
                      + ((oc & 7) * 4 + (ic & 3))) * 2 + ((ic >> 2) & 1);
    const float b = w2b[row];
#pragma unroll
    for (int pi = 0; pi < 4; pi++) {
        float lo, hi;
        unpk2(acc2[pi], lo, hi);
        const int s0 = sg * 8 + 2 * pi;
        g_wt2[(size_t)s0 * WFLAT + frag]       = rna_tf32(lo + b);
        g_wt2[(size_t)(s0 + 1) * WFLAT + frag] = rna_tf32(hi + b);
    }
}

// ---------------------------------------------------------------------------
// convk: tf32 mma.sync implicit GEMM.
// CTA: 128 px x 64 oc for one sample. A slab (64ic x 322px, stride 328) staged
// ONCE covering all 9 shifts; B (fragment order) staged per kk.
// grid=(72, 32), block=128 (4 warps; warp w owns px [32w, 32w+32)).
// ---------------------------------------------------------------------------
#define ASTRIDE 328
#define SM_B_OFF (64 * ASTRIDE)                 // floats
#define SMEM_REQ ((64 * ASTRIDE + 4096) * 4)    // 100,352 B

__global__ __launch_bounds__(128) void convk(const float* __restrict__ x,
                                             float* __restrict__ out) {
    extern __shared__ float S[];
    float* sA = S;
    float* sB = S + SM_B_OFF;

    const int tid  = threadIdx.x;
    const int lane = tid & 31, wrp = tid >> 5;
    const int s    = blockIdx.y;
    const int p0   = blockIdx.x * 128;
    const u32 xs0  = (u32)s * (64u * NPIX);

    // ---- stage A once: 64 ic x 322 px, tf32-rounded, conflict-free layout ----
#pragma unroll 1
    for (int ic = 0; ic < 64; ic++) {
        const u32 rb = xs0 + (u32)ic * NPIX + (u32)p0;
#pragma unroll
        for (int j = tid * 2; j < 322; j += 256) {
            u32 idx = rb + (u32)j;
            if (idx > XMAXI - 1u) idx = XMAXI - 1u;
            float2 v = *(const float2*)(x + idx);
            sA[ic * ASTRIDE + j]     = rna_tf32(v.x);
            sA[ic * ASTRIDE + j + 1] = rna_tf32(v.y);
        }
    }

    float acc[2][8][4];
#pragma unroll
    for (int mt = 0; mt < 2; mt++)
#pragma unroll
        for (int nt = 0; nt < 8; nt++)
#pragma unroll
            for (int r = 0; r < 4; r++) acc[mt][nt][r] = 0.f;

    // per-thread A fragment base: ic = lane&3 rows, px = lane>>2
    const int abase = (lane & 3) * ASTRIDE + (lane >> 2) + wrp * 32;

#pragma unroll 1
    for (int kk = 0; kk < 9; kk++) {
        const int off = (kk / 3) * 96 + (kk % 3);
        __syncthreads();   // sB from previous kk fully consumed (also orders sA once)
        // ---- stage B: 4096 floats, fragment-ordered, coalesced copy ----
        {
            const float4* gB = (const float4*)(g_wt2 + ((size_t)s * 9 + kk) * 4096);
            float4* sB4 = (float4*)sB;
#pragma unroll
            for (int it = 0; it < 8; it++)
                sB4[it * 128 + tid] = gB[it * 128 + tid];
        }
        __syncthreads();

#pragma unroll
        for (int ks = 0; ks < 8; ks++) {
            // B fragments: 8 n-tiles, LDS.64 conflict-free
            u32 b0[8], b1[8];
#pragma unroll
            for (int nt = 0; nt < 8; nt++) {
                float2 bv = *(const float2*)&sB[((ks * 8 + nt) * 32 + lane) * 2];
                b0[nt] = __float_as_uint(bv.x);
                b1[nt] = __float_as_uint(bv.y);
            }
#pragma unroll
            for (int mt = 0; mt < 2; mt++) {
                const int a = abase + ks * 8 * ASTRIDE + mt * 16 + off;
                const u32 a0 = __float_as_uint(sA[a]);
                const u32 a1 = __float_as_uint(sA[a + 8]);
                const u32 a2 = __float_as_uint(sA[a + 4 * ASTRIDE]);
                const u32 a3 = __float_as_uint(sA[a + 4 * ASTRIDE + 8]);
#pragma unroll
                for (int nt = 0; nt < 8; nt++)
                    mma8(acc[mt][nt], a0, a1, a2, a3, b0[nt], b1[nt]);
            }
        }
    }

    // ---- epilogue: D[px][oc]; mask h,w >= 94 ----
    const int pxw = p0 + wrp * 32 + (lane >> 2);
    const int oc0 = (lane & 3) * 2;
#pragma unroll
    for (int mt = 0; mt < 2; mt++) {
#pragma unroll
        for (int half = 0; half < 2; half++) {
            const int px = pxw + mt * 16 + half * 8;
            const int h = px / 96, w = px - h * 96;
            if (h < HOUT && w < HOUT) {
                float* op = out + ((size_t)s * 64) * 8836 + h * 94 + w;
#pragma unroll
                for (int nt = 0; nt < 8; nt++) {
                    op[(nt * 8 + oc0 + 0) * 8836] = acc[mt][nt][half * 2 + 0];
                    op[(nt * 8 + oc0 + 1) * 8836] = acc[mt][nt][half * 2 + 1];
                }
            }
        }
    }
}

// ---------------------------------------------------------------------------
extern "C" void kernel_launch(void* const* d_in, const int* in_sizes, int n_in,
                              void* d_out, int out_size) {
    const float* emb = (const float*)d_in[0];
    const float* x   = (const float*)d_in[1];
    const float* w1w = (const float*)d_in[2];
    const float* w1b = (const float*)d_in[3];
    const float* w2w = (const float*)d_in[4];
    const float* w2b = (const float*)d_in[5];
    float* out = (float*)d_out;

    cudaFuncSetAttribute(convk, cudaFuncAttributeMaxDynamicSharedMemorySize, SMEM_REQ);

    hyper1<<<256, 256>>>(emb, w1w, w1b);
    hyper2<<<WFLAT / 32, 128>>>(w2w, w2b);
    convk<<<dim3(72, 32), 128, SMEM_REQ>>>(x, out);
}

// round 6
// speedup vs baseline: 5.7877x; 3.3565x over previous
#include <cuda_runtime.h>
#include <cuda_fp16.h>
#include <cstdint>

#define BS    32
#define EMB   512
#define GL    256
#define WFLAT 36864
#define HIN   96
#define HOUT  94
#define NPIX  9216
#define XCLAMP (32u*64u*9216u - 4u)

typedef unsigned long long u64;
typedef unsigned int u32;

__device__ __align__(16) float  g_hdn_t[GL * BS];
// B in fp16 mma-fragment order: [s][kk][ks(4)][nt(8)][lane(32)][reg(2)][half(2)]
__device__ __align__(16) __half g_wB[BS * WFLAT];

// ---- helpers ----------------------------------------------------------------
__device__ __forceinline__ void fma2(u64& d, u64 a, u64 b) {
    asm("fma.rn.f32x2 %0, %1, %2, %0;" : "+l"(d) : "l"(a), "l"(b));
}
__device__ __forceinline__ void unpk2(u64 v, float& lo, float& hi) {
    asm("mov.b64 {%0, %1}, %2;" : "=f"(lo), "=f"(hi) : "l"(v));
}
__device__ __forceinline__ u32 smem_u32(const void* p) {
    u32 a; asm("{ .reg .u64 t; cvta.to.shared.u64 t, %1; cvt.u32.u64 %0, t; }" : "=r"(a) : "l"(p));
    return a;
}
__device__ __forceinline__ void cpa16(u32 dst, const void* src) {
    asm volatile("cp.async.cg.shared.global [%0], [%1], 16;" :: "r"(dst), "l"(src));
}
#define CPA_COMMIT() asm volatile("cp.async.commit_group;" ::: "memory")
#define CPA_WAIT(N)  asm volatile("cp.async.wait_group %0;" :: "n"(N) : "memory")

// fp16 warp MMA: D(16x8,f32) += A(16x16,f16) * B(16x8,f16)
__device__ __forceinline__ void mma16(float* c, u32 a0, u32 a1, u32 a2, u32 a3,
                                      u32 b0, u32 b1) {
    asm("mma.sync.aligned.m16n8k16.row.col.f32.f16.f16.f32 "
        "{%0,%1,%2,%3}, {%4,%5,%6,%7}, {%8,%9}, {%0,%1,%2,%3};"
        : "+f"(c[0]), "+f"(c[1]), "+f"(c[2]), "+f"(c[3])
        : "r"(a0), "r"(a1), "r"(a2), "r"(a3), "r"(b0), "r"(b1));
}

// ---------------------------------------------------------------------------
// hyper1: hdn_t[j][s] = relu(emb[s,:]·w1[j,:] + b1[j])
// ---------------------------------------------------------------------------
__global__ __launch_bounds__(256) void hyper1(const float* __restrict__ emb,
                                              const float* __restrict__ w1w,
                                              const float* __restrict__ w1b) {
    __shared__ float red[8][33];
    const int tid = threadIdx.x;
    const int s = blockIdx.x >> 3, jg = blockIdx.x & 7;
    const int lane = tid & 31, slice = tid >> 5;
    const int j = jg * 32 + lane;
    const float4* wr = (const float4*)(w1w + (size_t)j * EMB + slice * 64);
    const float4* er = (const float4*)(emb + (size_t)s * EMB + slice * 64);
    float acc = 0.f;
#pragma unroll
    for (int k = 0; k < 16; k++) {
        float4 w = wr[k], e = er[k];
        acc += w.x * e.x + w.y * e.y + w.z * e.z + w.w * e.w;
    }
    red[slice][lane] = acc;
    __syncthreads();
    if (tid < 32) {
        float a = 0.f;
#pragma unroll
        for (int t = 0; t < 8; t++) a += red[t][tid];
        const int jj = jg * 32 + tid;
        a += w1b[jj];
        g_hdn_t[jj * BS + s] = a > 0.f ? a : 0.f;
    }
}

// ---------------------------------------------------------------------------
// hyper2: weight GEMM; epilogue writes fp16 values in m16n8k16 B-fragment order.
//   row = oc*576 + ic*9 + kk;  ks=ic>>4, kpos=ic&15, reg=kpos>>3, klo=kpos&7
//   lane=(oc&7)*4+(klo>>1), half=klo&1, nt=oc>>3
//   frag = ((((kk*4+ks)*8+nt)*32+lane)*2+reg)*2 + half
// ---------------------------------------------------------------------------
__global__ __launch_bounds__(128) void hyper2(const float* __restrict__ w2w,
                                              const float* __restrict__ w2b) {
    __shared__ float hdn_sm[GL * BS];
    __shared__ __align__(16) float2 w2td[64 * 33];

    const int tid = threadIdx.x;
    const int lane = tid & 31, sg = tid >> 5;
    const int r0 = blockIdx.x * 32;

#pragma unroll
    for (int it = 0; it < 16; it++)
        ((float4*)hdn_sm)[it * 128 + tid] = ((const float4*)g_hdn_t)[it * 128 + tid];

    u64 acc2[4];
#pragma unroll
    for (int i = 0; i < 4; i++) acc2[i] = 0ull;

    for (int kc = 0; kc < 4; kc++) {
        __syncthreads();
#pragma unroll
        for (int it = 0; it < 16; it++) {
            int idx = it * 128 + tid;
            int r = idx >> 6, kk = idx & 63;
            float v = w2w[(size_t)(r0 + r) * GL + kc * 64 + kk];
            w2td[kk * 33 + r] = make_float2(v, v);
        }
        __syncthreads();
#pragma unroll
        for (int k = 0; k < 64; k++) {
            const u64 wd = *(const u64*)&w2td[k * 33 + lane];
            const float* hb = &hdn_sm[(kc * 64 + k) * BS + sg * 8];
            fma2(acc2[0], wd, *(const u64*)&hb[0]);
            fma2(acc2[1], wd, *(const u64*)&hb[2]);
            fma2(acc2[2], wd, *(const u64*)&hb[4]);
            fma2(acc2[3], wd, *(const u64*)&hb[6]);
        }
    }

    const int row = r0 + lane;          // row = oc*576 + ic*9 + kk
    const int oc  = row / 576;
    const int rem = row - oc * 576;
    const int ic  = rem / 9;
    const int kk  = rem - ic * 9;
    const int ks = ic >> 4, kpos = ic & 15;
    const int reg = kpos >> 3, klo = kpos & 7;
    const int lanef = (oc & 7) * 4 + (klo >> 1);
    const int nt = oc >> 3, hsel = klo & 1;
    const int frag = ((((kk * 4 + ks) * 8 + nt) * 32 + lanef) * 2 + reg) * 2 + hsel;
    const float b = w2b[row];
#pragma unroll
    for (int pi = 0; pi < 4; pi++) {
        float lo, hi;
        unpk2(acc2[pi], lo, hi);
        const int s0 = sg * 8 + 2 * pi;
        g_wB[(size_t)s0 * WFLAT + frag]       = __float2half_rn(lo + b);
        g_wB[(size_t)(s0 + 1) * WFLAT + frag] = __float2half_rn(hi + b);
    }
}

// ---------------------------------------------------------------------------
// convk: fp16 mma.sync implicit GEMM. 128 px x 64 oc per CTA, one sample.
// A slab (32 icpairs x 322 px, half2, stride 328) staged once, MLP-parallel.
// B double-buffered via cp.async. grid=(72,32), block=128.
// ---------------------------------------------------------------------------
#define ASTR 328                              // half2 units per icpair row
#define SMA_BYTES (32 * ASTR * 4)             // 41984
#define SMEM_REQ  (SMA_BYTES + 2 * 8192)      // 58368

__global__ __launch_bounds__(128) void convk(const float* __restrict__ x,
                                             float* __restrict__ out) {
    extern __shared__ char S[];
    half2*  sA = (half2*)S;
    __half* sB = (__half*)(S + SMA_BYTES);
    const u32 sBu = smem_u32(S) + SMA_BYTES;

    const int tid  = threadIdx.x;
    const int lane = tid & 31, wrp = tid >> 5;
    const int s    = blockIdx.y;
    const int p0   = blockIdx.x * 128;
    const u32 xs0  = (u32)s * (64u * NPIX);

    // ---- stage A: 32 icpairs x 322 px, fully unrolled (MLP ~24 LDG/thread) ----
#pragma unroll
    for (int ipl = 0; ipl < 8; ipl++) {
        const int ip  = wrp * 8 + ipl;
        const u32 r0b = xs0 + (u32)(2 * ip) * NPIX + (u32)p0;
#pragma unroll
        for (int c = 0; c < 3; c++) {
            const int px = c * 128 + lane * 4;
            u32 i0 = r0b + (u32)px;          if (i0 > XCLAMP) i0 = XCLAMP;
            u32 i1 = r0b + NPIX + (u32)px;   if (i1 > XCLAMP) i1 = XCLAMP;
            const float4 v0 = *(const float4*)(x + i0);
            const float4 v1 = *(const float4*)(x + i1);
            if (px < 326) {
                half2 h[4];
                h[0] = __floats2half2_rn(v0.x, v1.x);
                h[1] = __floats2half2_rn(v0.y, v1.y);
                h[2] = __floats2half2_rn(v0.z, v1.z);
                h[3] = __floats2half2_rn(v0.w, v1.w);
                *(uint4*)&sA[ip * ASTR + px] = *(const uint4*)h;
            }
        }
    }

    // ---- prologue: prefetch B for kk=0 ----
    {
        const char* src = (const char*)(g_wB + ((size_t)s * 9 + 0) * 4096);
#pragma unroll
        for (int i = 0; i < 4; i++)
            cpa16(sBu + (u32)((i * 128 + tid) * 16), src + (i * 128 + tid) * 16);
        CPA_COMMIT();
    }

    float acc[2][8][4];
#pragma unroll
    for (int mt = 0; mt < 2; mt++)
#pragma unroll
        for (int nt = 0; nt < 8; nt++)
#pragma unroll
            for (int r = 0; r < 4; r++) acc[mt][nt][r] = 0.f;

    const int pxb = wrp * 32 + (lane >> 2);

#pragma unroll 1
    for (int kk = 0; kk < 9; kk++) {
        if (kk < 8) {   // prefetch kk+1 into other buffer
            const char* src = (const char*)(g_wB + ((size_t)s * 9 + kk + 1) * 4096);
            const u32 dst = sBu + (u32)(((kk + 1) & 1) * 8192);
#pragma unroll
            for (int i = 0; i < 4; i++)
                cpa16(dst + (u32)((i * 128 + tid) * 16), src + (i * 128 + tid) * 16);
            CPA_COMMIT();
            CPA_WAIT(1);
        } else {
            CPA_WAIT(0);
        }
        __syncthreads();

        const int off = (kk / 3) * 96 + (kk % 3);
        const __half* B = sB + (kk & 1) * 4096;

#pragma unroll
        for (int ks = 0; ks < 4; ks++) {
            u32 b0[8], b1[8];
#pragma unroll
            for (int nt = 0; nt < 8; nt++) {
                const uint2 bv = *(const uint2*)&B[((ks * 8 + nt) * 32 + lane) * 4];
                b0[nt] = bv.x; b1[nt] = bv.y;
            }
#pragma unroll
            for (int mt = 0; mt < 2; mt++) {
                const int a = (ks * 8 + (lane & 3)) * ASTR + pxb + mt * 16 + off;
                const u32 a0 = *(const u32*)&sA[a];
                const u32 a1 = *(const u32*)&sA[a + 8];
                const u32 a2 = *(const u32*)&sA[a + 4 * ASTR];
                const u32 a3 = *(const u32*)&sA[a + 4 * ASTR + 8];
#pragma unroll
                for (int nt = 0; nt < 8; nt++)
                    mma16(acc[mt][nt], a0, a1, a2, a3, b0[nt], b1[nt]);
            }
        }
        __syncthreads();
    }

    // ---- epilogue: D[px][oc]; mask h,w >= 94 ----
    const int pxw = p0 + pxb;
    const int oc0 = (lane & 3) * 2;
#pragma unroll
    for (int mt = 0; mt < 2; mt++) {
#pragma unroll
        for (int half = 0; half < 2; half++) {
            const int px = pxw + mt * 16 + half * 8;
            const int h = px / 96, w = px - h * 96;
            if (h < HOUT && w < HOUT) {
                float* op = out + ((size_t)s * 64) * 8836 + h * 94 + w;
#pragma unroll
                for (int nt = 0; nt < 8; nt++) {
                    op[(nt * 8 + oc0 + 0) * 8836] = acc[mt][nt][half * 2 + 0];
                    op[(nt * 8 + oc0 + 1) * 8836] = acc[mt][nt][half * 2 + 1];
                }
            }
        }
    }
}

// ---------------------------------------------------------------------------
extern "C" void kernel_launch(void* const* d_in, const int* in_sizes, int n_in,
                              void* d_out, int out_size) {
    const float* emb = (const float*)d_in[0];
    const float* x   = (const float*)d_in[1];
    const float* w1w = (const float*)d_in[2];
    const float* w1b = (const float*)d_in[3];
    const float* w2w = (const float*)d_in[4];
    const float* w2b = (const float*)d_in[5];
    float* out = (float*)d_out;

    cudaFuncSetAttribute(convk, cudaFuncAttributeMaxDynamicSharedMemorySize, SMEM_REQ);

    hyper1<<<256, 256>>>(emb, w1w, w1b);
    hyper2<<<WFLAT / 32, 128>>>(w2w, w2b);
    convk<<<dim3(72, 32), 128, SMEM_REQ>>>(x, out);
}